// round 17
// baseline (speedup 1.0000x reference)
#include <cuda_runtime.h>
#include <cuda_bf16.h>
#include <math.h>
#include <stdint.h>

#define NROWS 256
#define DLEN  196608               // 3*256*256
#define CHUNKS 4
#define TPB   512
#define NBLK  (NROWS * CHUNKS)
#define F4_PER_CHUNK (DLEN / 4 / CHUNKS)   // 12288 float4 per chunk per stream
#define STAGE_F4  TPB                      // 512 float4 = 8 KB per stream per stage
#define NSTAGES   (F4_PER_CHUNK / STAGE_F4) // 24
#define STAGE_BYTES (STAGE_F4 * 16)        // 8192
#define STAGE_TX    (2 * STAGE_BYTES)      // z + b per stage

// scratch: per (row,chunk) partials [Sz, Sb, Szz, Sbb, Szb]
__device__ float g_part[NBLK][5];
__device__ unsigned int g_done = 0;        // reset by the finalizing block each launch

__device__ __forceinline__ void acc5(const float4 zv, const float4 bv,
                                     float& sz, float& sb, float& szz, float& sbb, float& szb) {
    sz  += (zv.x + zv.y) + (zv.z + zv.w);
    sb  += (bv.x + bv.y) + (bv.z + bv.w);
    szz  = fmaf(zv.x, zv.x, fmaf(zv.y, zv.y, fmaf(zv.z, zv.z, fmaf(zv.w, zv.w, szz))));
    sbb  = fmaf(bv.x, bv.x, fmaf(bv.y, bv.y, fmaf(bv.z, bv.z, fmaf(bv.w, bv.w, sbb))));
    szb  = fmaf(zv.x, bv.x, fmaf(zv.y, bv.y, fmaf(zv.z, bv.z, fmaf(zv.w, bv.w, szb))));
}

__device__ __forceinline__ void mbar_init(uint32_t addr, uint32_t count) {
    asm volatile("mbarrier.init.shared.b64 [%0], %1;" :: "r"(addr), "r"(count) : "memory");
}
__device__ __forceinline__ void mbar_expect_tx(uint32_t addr, uint32_t bytes) {
    asm volatile("mbarrier.arrive.expect_tx.shared.b64 _, [%0], %1;"
                 :: "r"(addr), "r"(bytes) : "memory");
}
__device__ __forceinline__ void bulk_g2s(uint32_t dst_smem, const void* src_gmem,
                                         uint32_t bytes, uint32_t mbar) {
    asm volatile(
        "cp.async.bulk.shared::cta.global.mbarrier::complete_tx::bytes [%0], [%1], %2, [%3];"
        :: "r"(dst_smem), "l"(src_gmem), "r"(bytes), "r"(mbar) : "memory");
}
__device__ __forceinline__ void mbar_wait_parity(uint32_t addr, uint32_t parity) {
    uint32_t done;
    asm volatile(
        "{\n\t.reg .pred p;\n\t"
        "mbarrier.try_wait.parity.acquire.cta.shared::cta.b64 p, [%1], %2;\n\t"
        "selp.b32 %0, 1, 0, p;\n\t}"
        : "=r"(done) : "r"(addr), "r"(parity) : "memory");
    if (!done) {
        asm volatile(
            "{\n\t.reg .pred P1;\n\t"
            "WL_%=:\n\t"
            "mbarrier.try_wait.parity.acquire.cta.shared::cta.b64 P1, [%0], %1, 0x989680;\n\t"
            "@P1 bra.uni WD_%=;\n\t"
            "bra.uni WL_%=;\n\t"
            "WD_%=:\n\t}"
            :: "r"(addr), "r"(parity) : "memory");
    }
}

__global__ __launch_bounds__(TPB)
void pixcorr_tma(const float* __restrict__ preds, const float* __restrict__ targ,
                 float* __restrict__ out) {
    __shared__ __align__(16) float4 bufz[2][STAGE_F4];   // 16 KB
    __shared__ __align__(16) float4 bufb[2][STAGE_F4];   // 16 KB
    __shared__ __align__(8)  unsigned long long mbar[2];
    __shared__ float sm[5][TPB / 32];
    __shared__ bool is_last;

    const int tid   = threadIdx.x;
    const int blk   = blockIdx.x;          // 0..1023
    const int row   = blk >> 2;
    const int chunk = blk & 3;

    const float4* __restrict__ z4 =
        reinterpret_cast<const float4*>(targ) + (size_t)row * (DLEN / 4) + (size_t)chunk * F4_PER_CHUNK;
    const float4* __restrict__ b4 =
        reinterpret_cast<const float4*>(preds) + (size_t)row * (DLEN / 4) + (size_t)chunk * F4_PER_CHUNK;

    const uint32_t mb0 = (uint32_t)__cvta_generic_to_shared(&mbar[0]);
    const uint32_t mb1 = (uint32_t)__cvta_generic_to_shared(&mbar[1]);
    const uint32_t sz0 = (uint32_t)__cvta_generic_to_shared(&bufz[0][0]);
    const uint32_t sz1 = (uint32_t)__cvta_generic_to_shared(&bufz[1][0]);
    const uint32_t sb0 = (uint32_t)__cvta_generic_to_shared(&bufb[0][0]);
    const uint32_t sb1 = (uint32_t)__cvta_generic_to_shared(&bufb[1][0]);

    if (tid == 0) {
        mbar_init(mb0, 1);
        mbar_init(mb1, 1);
    }
    __syncthreads();

    if (tid == 0) {
        // prologue: fill both stages
        mbar_expect_tx(mb0, STAGE_TX);
        bulk_g2s(sz0, z4,              STAGE_BYTES, mb0);
        bulk_g2s(sb0, b4,              STAGE_BYTES, mb0);
        mbar_expect_tx(mb1, STAGE_TX);
        bulk_g2s(sz1, z4 + STAGE_F4,   STAGE_BYTES, mb1);
        bulk_g2s(sb1, b4 + STAGE_F4,   STAGE_BYTES, mb1);
    }

    float sza = 0.f, sba = 0.f, szz = 0.f, sbb = 0.f, szb = 0.f;

    for (int k = 0; k < NSTAGES; k++) {
        const int s = k & 1;
        const uint32_t ph = (uint32_t)((k >> 1) & 1);
        mbar_wait_parity(s ? mb1 : mb0, ph);

        float4 zv = bufz[s][tid];
        float4 bv = bufb[s][tid];
        acc5(zv, bv, sza, sba, szz, sbb, szb);

        __syncthreads();                   // all consumers done with stage s
        if (tid == 0 && k + 2 < NSTAGES) {
            const uint32_t mb = s ? mb1 : mb0;
            mbar_expect_tx(mb, STAGE_TX);
            bulk_g2s(s ? sz1 : sz0, z4 + (size_t)(k + 2) * STAGE_F4, STAGE_BYTES, mb);
            bulk_g2s(s ? sb1 : sb0, b4 + (size_t)(k + 2) * STAGE_F4, STAGE_BYTES, mb);
        }
    }

    // intra-warp butterfly reduction (5 values)
    #pragma unroll
    for (int o = 16; o > 0; o >>= 1) {
        sza += __shfl_xor_sync(0xFFFFFFFFu, sza, o);
        sba += __shfl_xor_sync(0xFFFFFFFFu, sba, o);
        szz += __shfl_xor_sync(0xFFFFFFFFu, szz, o);
        sbb += __shfl_xor_sync(0xFFFFFFFFu, sbb, o);
        szb += __shfl_xor_sync(0xFFFFFFFFu, szb, o);
    }

    const int w = tid >> 5;
    const int l = tid & 31;
    if (l == 0) {
        sm[0][w] = sza; sm[1][w] = sba; sm[2][w] = szz; sm[3][w] = sbb; sm[4][w] = szb;
    }
    __syncthreads();

    if (tid < 5) {
        float a = 0.f;
        #pragma unroll
        for (int i = 0; i < TPB / 32; i++) a += sm[tid][i];
        g_part[blk][tid] = a;
    }

    // ---- last-block finalization (threadFenceReduction pattern) ----
    __syncthreads();
    if (tid == 0) {
        __threadfence();                   // publish this block's partials
        unsigned int old = atomicAdd(&g_done, 1u);
        is_last = (old == (unsigned int)(NBLK - 1));
    }
    __syncthreads();
    if (!is_last) return;

    __threadfence();                       // acquire: see all blocks' partials

    const int r = tid;
    __shared__ double smem[NROWS];
    if (r < NROWS) {
        double dsz = 0.0, dsb = 0.0, dszz = 0.0, dsbb = 0.0, dszb = 0.0;
        #pragma unroll
        for (int c = 0; c < CHUNKS; c++) {
            const float* p = g_part[r * CHUNKS + c];
            dsz  += (double)p[0];
            dsb  += (double)p[1];
            dszz += (double)p[2];
            dsbb += (double)p[3];
            dszb += (double)p[4];
        }
        const double Dd = (double)DLEN;
        const double num = dszb - dsz * dsb / Dd;
        const double vz  = dszz - dsz * dsz / Dd;
        const double vb  = dsbb - dsb * dsb / Dd;
        smem[r] = num / (sqrt(vz) * sqrt(vb) + 1e-6);
    }
    __syncthreads();

    // fixed-order pairwise tree over 256 rows: deterministic across replays
    #pragma unroll
    for (int s2 = NROWS / 2; s2 > 0; s2 >>= 1) {
        if (r < s2) smem[r] += smem[r + s2];
        __syncthreads();
    }
    if (r == 0) {
        out[0] = (float)(smem[0] / (double)NROWS);
        g_done = 0;                        // reset for next graph replay
    }
}

extern "C" void kernel_launch(void* const* d_in, const int* in_sizes, int n_in,
                              void* d_out, int out_size) {
    const float* preds = (const float*)d_in[0];
    const float* targ  = (const float*)d_in[1];
    float* out = (float*)d_out;

    pixcorr_tma<<<NBLK, TPB>>>(preds, targ, out);
}